// round 1
// baseline (speedup 1.0000x reference)
#include <cuda_runtime.h>
#include <cuda_bf16.h>
#include <math.h>

// Problem shape (fixed by the dataset):
//   x  : [8192, 2048]  (B=4, S=2048 flattened)
//   w1 : [2048, 2048], w3 : [2048, 2048], w2 : [2048, 2048]  (torch [out,in])
//   wr : [8, 2048]
// out : [8192, 2048] but ONLY rows 0..7 are nonzero (scatter target = expert id).
//
// Pipeline:
//   1) zero-fill out
//   2) routing: logits = x @ wr^T, softmax, top-2, gates -> C[n][e] coeffs
//   3) bufA = silu(x   @ w1^T)
//   4) bufB = silu(bufA@ w3^T)
//   5) bufA =      bufB@ w2^T
//   6) partial[by][e][col] = sum over token-block of C[n][e]*bufA[n][col]
//   7) out[e][col] = sum_by partial  (deterministic two-stage reduction)

#define NTOK  8192
#define DIM   2048
#define NEXP  8

#define BM 128
#define BN 128
#define BK 16
#define TM 8
#define TN 8
#define GEMM_THREADS 256   // (BM/TM)*(BN/TN)

// ---- scratch (static device globals; no allocations allowed) ----
__device__ float g_bufA[(size_t)NTOK * DIM];
__device__ float g_bufB[(size_t)NTOK * DIM];
__device__ float g_C[(size_t)NTOK * NEXP];           // per-token expert coefficients
__device__ float g_part[(size_t)(NTOK / BM) * NEXP * DIM];  // 64 x 8 x 2048 partials

// ---------------------------------------------------------------------------
// zero-fill output (float4 grid-stride)
// ---------------------------------------------------------------------------
__global__ void zero_kernel(float4* __restrict__ out, size_t n4) {
    size_t i = (size_t)blockIdx.x * blockDim.x + threadIdx.x;
    size_t stride = (size_t)gridDim.x * blockDim.x;
    float4 z = make_float4(0.f, 0.f, 0.f, 0.f);
    for (; i < n4; i += stride) out[i] = z;
}

// ---------------------------------------------------------------------------
// routing: one warp per token. logits[e] = sum_k x[n,k]*wr[e,k];
// softmax -> top-2 (jax tie-break: lowest index first) -> normalized gates.
// Writes C[n][e] = gate if e in top-2 else 0.
// ---------------------------------------------------------------------------
__global__ void routing_kernel(const float* __restrict__ x,
                               const float* __restrict__ wr,
                               float* __restrict__ C) {
    int gwarp = (blockIdx.x * blockDim.x + threadIdx.x) >> 5;
    int lane  = threadIdx.x & 31;
    if (gwarp >= NTOK) return;

    const float* xr = x + (size_t)gwarp * DIM;
    float acc[NEXP];
#pragma unroll
    for (int e = 0; e < NEXP; e++) acc[e] = 0.f;

    for (int k = lane; k < DIM; k += 32) {
        float xv = xr[k];
#pragma unroll
        for (int e = 0; e < NEXP; e++)
            acc[e] = fmaf(xv, wr[e * DIM + k], acc[e]);
    }
#pragma unroll
    for (int e = 0; e < NEXP; e++) {
#pragma unroll
        for (int off = 16; off > 0; off >>= 1)
            acc[e] += __shfl_xor_sync(0xffffffffu, acc[e], off);
    }
    if (lane == 0) {
        float m = acc[0];
#pragma unroll
        for (int e = 1; e < NEXP; e++) m = fmaxf(m, acc[e]);
        float p[NEXP];
#pragma unroll
        for (int e = 0; e < NEXP; e++) p[e] = expf(acc[e] - m);
        // top-1: strict > keeps lowest index on ties (matches lax.top_k)
        int e0 = 0; float p0 = p[0];
#pragma unroll
        for (int e = 1; e < NEXP; e++) if (p[e] > p0) { p0 = p[e]; e0 = e; }
        // top-2 among remaining
        int e1 = -1; float p1 = -1.f;
#pragma unroll
        for (int e = 0; e < NEXP; e++)
            if (e != e0 && p[e] > p1) { p1 = p[e]; e1 = e; }
        float inv = 1.f / (p0 + p1);
        float* Cn = C + (size_t)gwarp * NEXP;
#pragma unroll
        for (int e = 0; e < NEXP; e++) {
            float v = 0.f;
            if (e == e0) v = p0 * inv;
            else if (e == e1) v = p1 * inv;
            Cn[e] = v;
        }
    }
}

// ---------------------------------------------------------------------------
// C[M,Ncols] = A[M,K] * B[Ncols,K]^T   (both row-major, K contiguous)
// optional fused SiLU epilogue.
// 128x128 block tile, 8x8 per-thread, BK=16, register prefetch of next tile.
// ---------------------------------------------------------------------------
template <bool SILU>
__global__ void __launch_bounds__(GEMM_THREADS)
gemm_abT(const float* __restrict__ A, const float* __restrict__ B,
         float* __restrict__ Cmat, int M, int Ncols, int K) {
    __shared__ float As[BK][BM + 4];
    __shared__ float Bs[BK][BN + 4];

    const int bm = blockIdx.y * BM;
    const int bn = blockIdx.x * BN;
    const int tid = threadIdx.x;
    const int tx = tid & 15;   // 0..15 -> 8 cols each
    const int ty = tid >> 4;   // 0..15 -> 8 rows each

    float acc[TM][TN];
#pragma unroll
    for (int i = 0; i < TM; i++)
#pragma unroll
        for (int j = 0; j < TN; j++) acc[i][j] = 0.f;

    // global-load mapping: per tile, 512 float4 per matrix; thread loads f = tid, tid+256
    // f -> row = f>>2 (0..127), kq = f&3 (k-offset = kq*4)
    const int r0 = tid >> 2;          // row for f = tid
    const int q0 = tid & 3;
    const int r1 = (tid + 256) >> 2;  // row for f = tid+256
    const int q1 = (tid + 256) & 3;

    float4 pa0, pa1, pb0, pb1;

    // prologue: load k-tile 0
    pa0 = *(const float4*)(A + (size_t)(bm + r0) * K + q0 * 4);
    pa1 = *(const float4*)(A + (size_t)(bm + r1) * K + q1 * 4);
    pb0 = *(const float4*)(B + (size_t)(bn + r0) * K + q0 * 4);
    pb1 = *(const float4*)(B + (size_t)(bn + r1) * K + q1 * 4);

    for (int k0 = 0; k0 < K; k0 += BK) {
        // commit prefetched regs to smem (transposed)
        As[q0 * 4 + 0][r0] = pa0.x; As[q0 * 4 + 1][r0] = pa0.y;
        As[q0 * 4 + 2][r0] = pa0.z; As[q0 * 4 + 3][r0] = pa0.w;
        As[q1 * 4 + 0][r1] = pa1.x; As[q1 * 4 + 1][r1] = pa1.y;
        As[q1 * 4 + 2][r1] = pa1.z; As[q1 * 4 + 3][r1] = pa1.w;
        Bs[q0 * 4 + 0][r0] = pb0.x; Bs[q0 * 4 + 1][r0] = pb0.y;
        Bs[q0 * 4 + 2][r0] = pb0.z; Bs[q0 * 4 + 3][r0] = pb0.w;
        Bs[q1 * 4 + 0][r1] = pb1.x; Bs[q1 * 4 + 1][r1] = pb1.y;
        Bs[q1 * 4 + 2][r1] = pb1.z; Bs[q1 * 4 + 3][r1] = pb1.w;
        __syncthreads();

        const int kn = k0 + BK;
        if (kn < K) {  // prefetch next k-tile into registers
            pa0 = *(const float4*)(A + (size_t)(bm + r0) * K + kn + q0 * 4);
            pa1 = *(const float4*)(A + (size_t)(bm + r1) * K + kn + q1 * 4);
            pb0 = *(const float4*)(B + (size_t)(bn + r0) * K + kn + q0 * 4);
            pb1 = *(const float4*)(B + (size_t)(bn + r1) * K + kn + q1 * 4);
        }

#pragma unroll
        for (int kk = 0; kk < BK; kk++) {
            float ra[TM], rb[TN];
#pragma unroll
            for (int i = 0; i < TM; i++) ra[i] = As[kk][ty * TM + i];
#pragma unroll
            for (int j = 0; j < TN; j++) rb[j] = Bs[kk][tx * TN + j];
#pragma unroll
            for (int i = 0; i < TM; i++)
#pragma unroll
                for (int j = 0; j < TN; j++)
                    acc[i][j] = fmaf(ra[i], rb[j], acc[i][j]);
        }
        __syncthreads();
    }

#pragma unroll
    for (int i = 0; i < TM; i++) {
        const size_t rowoff = (size_t)(bm + ty * TM + i) * Ncols + bn + tx * TN;
#pragma unroll
        for (int j = 0; j < TN; j++) {
            float v = acc[i][j];
            if (SILU) v = v / (1.f + expf(-v));
            Cmat[rowoff + j] = v;
        }
    }
}

// ---------------------------------------------------------------------------
// stage-1 reduction: grid (DIM/128, NTOK/BM). Each thread owns one column,
// accumulates 8 expert partials over a 128-token block.
// ---------------------------------------------------------------------------
__global__ void reduce_partial_kernel(const float* __restrict__ h,
                                      const float* __restrict__ C,
                                      float* __restrict__ part) {
    const int col = blockIdx.x * 128 + threadIdx.x;
    const int n0 = blockIdx.y * BM;
    float acc[NEXP];
#pragma unroll
    for (int e = 0; e < NEXP; e++) acc[e] = 0.f;

    for (int i = 0; i < BM; i++) {
        const int n = n0 + i;
        const float hv = h[(size_t)n * DIM + col];
        const float* Cn = C + (size_t)n * NEXP;  // broadcast across warp via L1
#pragma unroll
        for (int e = 0; e < NEXP; e++)
            acc[e] = fmaf(hv, Cn[e], acc[e]);
    }
#pragma unroll
    for (int e = 0; e < NEXP; e++)
        part[((size_t)blockIdx.y * NEXP + e) * DIM + col] = acc[e];
}

// stage-2: out[e][col] = sum over 64 token-blocks (deterministic order)
__global__ void reduce_final_kernel(const float* __restrict__ part,
                                    float* __restrict__ out) {
    const int id = blockIdx.x * blockDim.x + threadIdx.x;  // 0..NEXP*DIM-1
    if (id >= NEXP * DIM) return;
    const int e = id / DIM;
    const int col = id % DIM;
    float s = 0.f;
#pragma unroll 4
    for (int by = 0; by < NTOK / BM; by++)
        s += part[((size_t)by * NEXP + e) * DIM + col];
    out[(size_t)e * DIM + col] = s;  // rows 0..7 overwritten; rest stay zero
}

// ---------------------------------------------------------------------------
extern "C" void kernel_launch(void* const* d_in, const int* in_sizes, int n_in,
                              void* d_out, int out_size) {
    const float* x  = (const float*)d_in[0];
    const float* w1 = (const float*)d_in[1];
    const float* w3 = (const float*)d_in[2];
    const float* w2 = (const float*)d_in[3];
    const float* wr = (const float*)d_in[4];
    float* out = (float*)d_out;

    float *bufA, *bufB, *C, *part;
    cudaGetSymbolAddress((void**)&bufA, g_bufA);
    cudaGetSymbolAddress((void**)&bufB, g_bufB);
    cudaGetSymbolAddress((void**)&C,    g_C);
    cudaGetSymbolAddress((void**)&part, g_part);

    // 1) zero entire output (poisoned by harness)
    {
        size_t n4 = (size_t)out_size / 4;
        int blocks = (int)((n4 + 255) / 256);
        if (blocks > 16384) blocks = 16384;
        zero_kernel<<<blocks, 256>>>((float4*)out, n4);
    }

    // 2) routing coefficients
    routing_kernel<<<(NTOK * 32) / 256, 256>>>(x, wr, C);

    // 3-5) FFN GEMM chain
    dim3 ggrid(DIM / BN, NTOK / BM);
    gemm_abT<true ><<<ggrid, GEMM_THREADS>>>(x,    w1, bufA, NTOK, DIM, DIM);
    gemm_abT<true ><<<ggrid, GEMM_THREADS>>>(bufA, w3, bufB, NTOK, DIM, DIM);
    gemm_abT<false><<<ggrid, GEMM_THREADS>>>(bufB, w2, bufA, NTOK, DIM, DIM);

    // 6-7) expert-weighted reduction into rows 0..7
    reduce_partial_kernel<<<dim3(DIM / 128, NTOK / BM), 128>>>(bufA, C, part);
    reduce_final_kernel<<<(NEXP * DIM + 255) / 256, 256>>>(part, out);
}

// round 5
// speedup vs baseline: 2.5287x; 2.5287x over previous
#include <cuda_runtime.h>
#include <cuda_bf16.h>
#include <math.h>
#include <stdint.h>

// ===========================================================================
// MoE layer via mma.sync bf16 split-precision (3-term) GEMMs.
// (tcgen05 is NOT available: harness compiles for compute_100, no 'a' suffix.)
//   x  : [8192, 2048] fp32    w1,w3,w2 : [2048,2048] fp32 (torch [out,in])
//   wr : [8, 2048]
// out[8192,2048]: only rows 0..7 nonzero (scatter target = expert id).
//
// R5 note: identical algorithm to R4 (which died to an infra-level "container
// failed twice" with no harness output; R2-vs-R3 evidence shows that failure
// mode masks unrelated causes). This is the controlled resubmission.
// ===========================================================================

#define NTOK  8192
#define DIM   2048
#define NEXP  8

// -------- GEMM tiling --------
#define TILE_M 128
#define TILE_N 128
#define KCH    64                       // bf16 elems per K-chunk (=128B row)
#define NCH_PASS (DIM / KCH)            // 32 chunks per pass
#define NPASS  3                        // hi*hi, lo*hi, hi*lo
#define NCHUNK (NCH_PASS * NPASS)       // 96
#define STAGES 4
#define A_BYTES (TILE_M * 128)          // 16 KB
#define B_BYTES (TILE_N * 128)          // 16 KB
#define STAGE_BYTES (A_BYTES + B_BYTES) // 32 KB
#define GTHREADS 256
#define GEMM_DYN_SMEM (STAGES * STAGE_BYTES)  // 128 KB

// -------- scratch (static device globals; runtime alloc is forbidden) ------
__device__ __nv_bfloat16 g_xh[(size_t)NTOK * DIM];   // x hi   (reused as act2 hi)
__device__ __nv_bfloat16 g_xl[(size_t)NTOK * DIM];   // x lo   (reused as act2 lo)
__device__ __nv_bfloat16 g_t1h[(size_t)NTOK * DIM];  // act1 hi
__device__ __nv_bfloat16 g_t1l[(size_t)NTOK * DIM];  // act1 lo
__device__ __nv_bfloat16 g_w1h[(size_t)DIM * DIM];
__device__ __nv_bfloat16 g_w1l[(size_t)DIM * DIM];
__device__ __nv_bfloat16 g_w3h[(size_t)DIM * DIM];
__device__ __nv_bfloat16 g_w3l[(size_t)DIM * DIM];
__device__ __nv_bfloat16 g_w2h[(size_t)DIM * DIM];
__device__ __nv_bfloat16 g_w2l[(size_t)DIM * DIM];
__device__ float g_h[(size_t)NTOK * DIM];            // final FFN output fp32
__device__ float g_C[(size_t)NTOK * NEXP];           // routing coefficients
__device__ float g_part[(size_t)(NTOK / 128) * NEXP * DIM];

// ===========================================================================
// helpers
// ===========================================================================
__device__ __forceinline__ uint32_t smem_u32(const void* p) {
    uint32_t a;
    asm("{ .reg .u64 t; cvta.to.shared.u64 t, %1; cvt.u32.u64 %0, t; }"
        : "=r"(a) : "l"(p));
    return a;
}
#define SWZ128(off) ((off) ^ (((off) >> 3) & 0x70))

__device__ __forceinline__ void cp_async16(uint32_t dst, const void* src) {
    asm volatile("cp.async.cg.shared.global [%0], [%1], 16;"
                 :: "r"(dst), "l"(src) : "memory");
}
__device__ __forceinline__ void cp_commit() {
    asm volatile("cp.async.commit_group;" ::: "memory");
}
template <int N>
__device__ __forceinline__ void cp_wait() {
    asm volatile("cp.async.wait_group %0;" :: "n"(N) : "memory");
}
__device__ __forceinline__ void ldmatrix_x4(uint32_t& r0, uint32_t& r1,
                                            uint32_t& r2, uint32_t& r3,
                                            uint32_t addr) {
    asm volatile("ldmatrix.sync.aligned.m8n8.x4.shared.b16 {%0,%1,%2,%3}, [%4];"
                 : "=r"(r0), "=r"(r1), "=r"(r2), "=r"(r3) : "r"(addr));
}
__device__ __forceinline__ void mma16816(float& d0, float& d1, float& d2, float& d3,
                                         uint32_t a0, uint32_t a1, uint32_t a2, uint32_t a3,
                                         uint32_t b0, uint32_t b1) {
    asm volatile(
        "mma.sync.aligned.m16n8k16.row.col.f32.bf16.bf16.f32 "
        "{%0,%1,%2,%3}, {%4,%5,%6,%7}, {%8,%9}, {%0,%1,%2,%3};"
        : "+f"(d0), "+f"(d1), "+f"(d2), "+f"(d3)
        : "r"(a0), "r"(a1), "r"(a2), "r"(a3), "r"(b0), "r"(b1));
}

// ===========================================================================
// split-precision GEMM:  C[M,N] = A[M,K] * B[N,K]^T  (fp32 via bf16 3-term)
//   mode 0: epilogue silu -> split into (OutH, OutL) bf16
//   mode 1: epilogue raw fp32 -> OutF
// ===========================================================================
__global__ void __launch_bounds__(GTHREADS, 1)
gemm_bf16x3(const __nv_bfloat16* __restrict__ Ah,
            const __nv_bfloat16* __restrict__ Al,
            const __nv_bfloat16* __restrict__ Bh,
            const __nv_bfloat16* __restrict__ Bl,
            __nv_bfloat16* __restrict__ OutH,
            __nv_bfloat16* __restrict__ OutL,
            float* __restrict__ OutF,
            int mode) {
    extern __shared__ char dynsm[];
    const uint32_t sm_base = smem_u32(dynsm);

    const int tid    = threadIdx.x;
    const int wid    = tid >> 5;
    const int lane   = tid & 31;
    const int warp_m = wid & 3;    // 4 row-warps: 32 rows each
    const int warp_n = wid >> 2;   // 2 col-warps: 64 cols each
    const int bm = blockIdx.y * TILE_M;
    const int bn = blockIdx.x * TILE_N;

    // fp32 accumulators: 2 m-tiles (16) x 8 n-tiles (8) x 4 regs
    float acc[2][8][4];
#pragma unroll
    for (int i = 0; i < 2; i++)
#pragma unroll
        for (int j = 0; j < 8; j++)
#pragma unroll
            for (int r = 0; r < 4; r++) acc[i][j][r] = 0.f;

    // ldmatrix per-lane byte offsets within a tile (before k16 advance+swizzle)
    uint32_t a_off[2], b_off[4];
#pragma unroll
    for (int mi = 0; mi < 2; mi++) {
        const int row = warp_m * 32 + mi * 16 + (lane & 15);
        a_off[mi] = row * 128 + (lane >> 4) * 16;
    }
#pragma unroll
    for (int g = 0; g < 4; g++) {
        const int row = warp_n * 64 + g * 16 + (lane & 15);
        b_off[g] = row * 128 + (lane >> 4) * 16;
    }

    // cp.async mapping: 1024 16B chunks per tile, 4 per thread per tile
    auto issue_chunk = [&](int c) {
        const int pass = c >> 5;            // 0: Ah*Bh  1: Al*Bh  2: Ah*Bl
        const int k0   = (c & 31) * KCH;
        const uint32_t stage = sm_base + (uint32_t)(c & (STAGES - 1)) * STAGE_BYTES;
        const __nv_bfloat16* Asrc = (pass == 1) ? Al : Ah;
        const __nv_bfloat16* Bsrc = (pass == 2) ? Bl : Bh;
#pragma unroll
        for (int i = 0; i < 4; i++) {
            const int f = tid + i * 256;
            const int r = f >> 3, v = f & 7;
            cp_async16(stage + SWZ128(r * 128 + v * 16),
                       Asrc + (size_t)(bm + r) * DIM + k0 + v * 8);
        }
#pragma unroll
        for (int i = 0; i < 4; i++) {
            const int f = tid + i * 256;
            const int r = f >> 3, v = f & 7;
            cp_async16(stage + A_BYTES + SWZ128(r * 128 + v * 16),
                       Bsrc + (size_t)(bn + r) * DIM + k0 + v * 8);
        }
    };

    // prologue: chunks 0..STAGES-2, one commit group each
#pragma unroll
    for (int c = 0; c < STAGES - 1; c++) { issue_chunk(c); cp_commit(); }

    for (int c = 0; c < NCHUNK; c++) {
        cp_wait<STAGES - 2>();   // chunk c's group complete (this thread)
        __syncthreads();         // publish all copies; compute(c-1) fully done
        const int nc = c + STAGES - 1;
        if (nc < NCHUNK) issue_chunk(nc);
        cp_commit();             // one group per iteration (possibly empty)

        const uint32_t sA = sm_base + (uint32_t)(c & (STAGES - 1)) * STAGE_BYTES;
        const uint32_t sB = sA + A_BYTES;
#pragma unroll
        for (int k16 = 0; k16 < 4; k16++) {
            const uint32_t kb = k16 * 32;
            uint32_t a[2][4];
#pragma unroll
            for (int mi = 0; mi < 2; mi++)
                ldmatrix_x4(a[mi][0], a[mi][1], a[mi][2], a[mi][3],
                            sA + SWZ128(a_off[mi] + kb));
            uint32_t b[4][4];
#pragma unroll
            for (int g = 0; g < 4; g++)
                ldmatrix_x4(b[g][0], b[g][1], b[g][2], b[g][3],
                            sB + SWZ128(b_off[g] + kb));
#pragma unroll
            for (int mi = 0; mi < 2; mi++)
#pragma unroll
                for (int g = 0; g < 4; g++) {
                    mma16816(acc[mi][2*g][0], acc[mi][2*g][1],
                             acc[mi][2*g][2], acc[mi][2*g][3],
                             a[mi][0], a[mi][1], a[mi][2], a[mi][3],
                             b[g][0], b[g][2]);
                    mma16816(acc[mi][2*g+1][0], acc[mi][2*g+1][1],
                             acc[mi][2*g+1][2], acc[mi][2*g+1][3],
                             a[mi][0], a[mi][1], a[mi][2], a[mi][3],
                             b[g][1], b[g][3]);
                }
        }
    }

    // ---- epilogue ----
    // fragment c0,c1 -> (row, col..col+1); c2,c3 -> (row+8, col..col+1)
#pragma unroll
    for (int mi = 0; mi < 2; mi++) {
        const int row0 = bm + warp_m * 32 + mi * 16 + (lane >> 2);
#pragma unroll
        for (int ni = 0; ni < 8; ni++) {
            const int col = bn + warp_n * 64 + ni * 8 + (lane & 3) * 2;
#pragma unroll
            for (int half = 0; half < 2; half++) {
                const int row = row0 + half * 8;
                const size_t idx = (size_t)row * DIM + col;
                float v0 = acc[mi][ni][half * 2 + 0];
                float v1 = acc[mi][ni][half * 2 + 1];
                if (mode == 0) {
                    v0 = v0 / (1.f + expf(-v0));
                    v1 = v1 / (1.f + expf(-v1));
                    __nv_bfloat16 h0 = __float2bfloat16(v0);
                    __nv_bfloat16 h1 = __float2bfloat16(v1);
                    __nv_bfloat16 l0 = __float2bfloat16(v0 - __bfloat162float(h0));
                    __nv_bfloat16 l1 = __float2bfloat16(v1 - __bfloat162float(h1));
                    *(__nv_bfloat162*)(OutH + idx) = __halves2bfloat162(h0, h1);
                    *(__nv_bfloat162*)(OutL + idx) = __halves2bfloat162(l0, l1);
                } else {
                    *(float2*)(OutF + idx) = make_float2(v0, v1);
                }
            }
        }
    }
}

// ===========================================================================
// fp32 -> (hi, lo) bf16 split, vectorized
// ===========================================================================
__global__ void split_kernel(const float4* __restrict__ in,
                             __nv_bfloat162* __restrict__ hi,
                             __nv_bfloat162* __restrict__ lo, int n4) {
    int i = blockIdx.x * blockDim.x + threadIdx.x;
    const int stride = gridDim.x * blockDim.x;
    for (; i < n4; i += stride) {
        float4 v = in[i];
        __nv_bfloat16 h0 = __float2bfloat16(v.x), h1 = __float2bfloat16(v.y);
        __nv_bfloat16 h2 = __float2bfloat16(v.z), h3 = __float2bfloat16(v.w);
        __nv_bfloat16 l0 = __float2bfloat16(v.x - __bfloat162float(h0));
        __nv_bfloat16 l1 = __float2bfloat16(v.y - __bfloat162float(h1));
        __nv_bfloat16 l2 = __float2bfloat16(v.z - __bfloat162float(h2));
        __nv_bfloat16 l3 = __float2bfloat16(v.w - __bfloat162float(h3));
        hi[2 * i]     = __halves2bfloat162(h0, h1);
        hi[2 * i + 1] = __halves2bfloat162(h2, h3);
        lo[2 * i]     = __halves2bfloat162(l0, l1);
        lo[2 * i + 1] = __halves2bfloat162(l2, l3);
    }
}

// ===========================================================================
// zero-fill output
// ===========================================================================
__global__ void zero_kernel(float4* __restrict__ out, size_t n4) {
    size_t i = (size_t)blockIdx.x * blockDim.x + threadIdx.x;
    size_t stride = (size_t)gridDim.x * blockDim.x;
    float4 z = make_float4(0.f, 0.f, 0.f, 0.f);
    for (; i < n4; i += stride) out[i] = z;
}

// ===========================================================================
// routing: one warp per token; softmax -> top2 -> normalized gates
// ===========================================================================
__global__ void routing_kernel(const float* __restrict__ x,
                               const float* __restrict__ wr,
                               float* __restrict__ C) {
    int gwarp = (blockIdx.x * blockDim.x + threadIdx.x) >> 5;
    int lane  = threadIdx.x & 31;
    if (gwarp >= NTOK) return;
    const float* xr = x + (size_t)gwarp * DIM;
    float acc[NEXP];
#pragma unroll
    for (int e = 0; e < NEXP; e++) acc[e] = 0.f;
    for (int k = lane; k < DIM; k += 32) {
        float xv = xr[k];
#pragma unroll
        for (int e = 0; e < NEXP; e++)
            acc[e] = fmaf(xv, wr[e * DIM + k], acc[e]);
    }
#pragma unroll
    for (int e = 0; e < NEXP; e++) {
#pragma unroll
        for (int off = 16; off > 0; off >>= 1)
            acc[e] += __shfl_xor_sync(0xffffffffu, acc[e], off);
    }
    if (lane == 0) {
        float m = acc[0];
#pragma unroll
        for (int e = 1; e < NEXP; e++) m = fmaxf(m, acc[e]);
        float p[NEXP];
#pragma unroll
        for (int e = 0; e < NEXP; e++) p[e] = expf(acc[e] - m);
        int e0 = 0; float p0 = p[0];
#pragma unroll
        for (int e = 1; e < NEXP; e++) if (p[e] > p0) { p0 = p[e]; e0 = e; }
        int e1 = -1; float p1 = -1.f;
#pragma unroll
        for (int e = 0; e < NEXP; e++)
            if (e != e0 && p[e] > p1) { p1 = p[e]; e1 = e; }
        float inv = 1.f / (p0 + p1);
        float* Cn = C + (size_t)gwarp * NEXP;
#pragma unroll
        for (int e = 0; e < NEXP; e++) {
            float v = 0.f;
            if (e == e0) v = p0 * inv;
            else if (e == e1) v = p1 * inv;
            Cn[e] = v;
        }
    }
}

// ===========================================================================
// expert-weighted reduction (two-stage, deterministic)
// ===========================================================================
__global__ void reduce_partial_kernel(const float* __restrict__ h,
                                      const float* __restrict__ C,
                                      float* __restrict__ part) {
    const int col = blockIdx.x * 128 + threadIdx.x;
    const int n0 = blockIdx.y * 128;
    float acc[NEXP];
#pragma unroll
    for (int e = 0; e < NEXP; e++) acc[e] = 0.f;
    for (int i = 0; i < 128; i++) {
        const int n = n0 + i;
        const float hv = h[(size_t)n * DIM + col];
        const float* Cn = C + (size_t)n * NEXP;
#pragma unroll
        for (int e = 0; e < NEXP; e++)
            acc[e] = fmaf(hv, Cn[e], acc[e]);
    }
#pragma unroll
    for (int e = 0; e < NEXP; e++)
        part[((size_t)blockIdx.y * NEXP + e) * DIM + col] = acc[e];
}

__global__ void reduce_final_kernel(const float* __restrict__ part,
                                    float* __restrict__ out) {
    const int id = blockIdx.x * blockDim.x + threadIdx.x;
    if (id >= NEXP * DIM) return;
    const int e = id / DIM;
    const int col = id % DIM;
    float s = 0.f;
#pragma unroll 4
    for (int by = 0; by < NTOK / 128; by++)
        s += part[((size_t)by * NEXP + e) * DIM + col];
    out[(size_t)e * DIM + col] = s;
}

// ===========================================================================
extern "C" void kernel_launch(void* const* d_in, const int* in_sizes, int n_in,
                              void* d_out, int out_size) {
    const float* x  = (const float*)d_in[0];
    const float* w1 = (const float*)d_in[1];
    const float* w3 = (const float*)d_in[2];
    const float* w2 = (const float*)d_in[3];
    const float* wr = (const float*)d_in[4];
    float* out = (float*)d_out;

    __nv_bfloat16 *xh, *xl, *t1h, *t1l, *w1h, *w1l, *w3h, *w3l, *w2h, *w2l;
    float *hbuf, *C, *part;
    cudaGetSymbolAddress((void**)&xh,  g_xh);
    cudaGetSymbolAddress((void**)&xl,  g_xl);
    cudaGetSymbolAddress((void**)&t1h, g_t1h);
    cudaGetSymbolAddress((void**)&t1l, g_t1l);
    cudaGetSymbolAddress((void**)&w1h, g_w1h);
    cudaGetSymbolAddress((void**)&w1l, g_w1l);
    cudaGetSymbolAddress((void**)&w3h, g_w3h);
    cudaGetSymbolAddress((void**)&w3l, g_w3l);
    cudaGetSymbolAddress((void**)&w2h, g_w2h);
    cudaGetSymbolAddress((void**)&w2l, g_w2l);
    cudaGetSymbolAddress((void**)&hbuf, g_h);
    cudaGetSymbolAddress((void**)&C,    g_C);
    cudaGetSymbolAddress((void**)&part, g_part);

    cudaFuncSetAttribute(gemm_bf16x3,
                         cudaFuncAttributeMaxDynamicSharedMemorySize,
                         GEMM_DYN_SMEM);

    // 1) zero output (harness poisons it)
    {
        size_t n4 = (size_t)out_size / 4;
        int blocks = (int)((n4 + 255) / 256);
        if (blocks > 16384) blocks = 16384;
        zero_kernel<<<blocks, 256>>>((float4*)out, n4);
    }

    // 2) routing coefficients (fp32, faithful top-k)
    routing_kernel<<<(NTOK * 32) / 256, 256>>>(x, wr, C);

    // 3) hi/lo splits
    const int nx4 = NTOK * DIM / 4, nw4 = DIM * DIM / 4;
    split_kernel<<<2048, 256>>>((const float4*)x,  (__nv_bfloat162*)xh,  (__nv_bfloat162*)xl,  nx4);
    split_kernel<<<1024, 256>>>((const float4*)w1, (__nv_bfloat162*)w1h, (__nv_bfloat162*)w1l, nw4);
    split_kernel<<<1024, 256>>>((const float4*)w3, (__nv_bfloat162*)w3h, (__nv_bfloat162*)w3l, nw4);
    split_kernel<<<1024, 256>>>((const float4*)w2, (__nv_bfloat162*)w2h, (__nv_bfloat162*)w2l, nw4);

    // 4) FFN chain on tensor cores (mma.sync path)
    dim3 ggrid(DIM / TILE_N, NTOK / TILE_M);  // (16, 64)
    gemm_bf16x3<<<ggrid, GTHREADS, GEMM_DYN_SMEM>>>(xh, xl, w1h, w1l,
                                                    t1h, t1l, nullptr, 0);
    gemm_bf16x3<<<ggrid, GTHREADS, GEMM_DYN_SMEM>>>(t1h, t1l, w3h, w3l,
                                                    xh, xl, nullptr, 0);   // reuse x bufs
    gemm_bf16x3<<<ggrid, GTHREADS, GEMM_DYN_SMEM>>>(xh, xl, w2h, w2l,
                                                    nullptr, nullptr, hbuf, 1);

    // 5) expert-weighted reduction into rows 0..7
    reduce_partial_kernel<<<dim3(DIM / 128, NTOK / 128), 128>>>(hbuf, C, part);
    reduce_final_kernel<<<(NEXP * DIM + 255) / 256, 256>>>(part, out);
}

// round 6
// speedup vs baseline: 2.6853x; 1.0619x over previous
#include <cuda_runtime.h>
#include <cuda_bf16.h>
#include <math.h>
#include <stdint.h>

// ===========================================================================
// MoE layer via mma.sync bf16 split-precision (3-term) GEMMs.
// (tcgen05 unavailable: harness compiles for compute_100, no 'a' suffix.)
// R6: 2 CTAs/SM (STAGES=3, 96KB smem) + double-buffered B fragments to close
//     the ~1.9x stall gap measured in R5 (1870 cyc/chunk vs ~770-1000 floor).
// ===========================================================================

#define NTOK  8192
#define DIM   2048
#define NEXP  8

// -------- GEMM tiling --------
#define TILE_M 128
#define TILE_N 128
#define KCH    64                       // bf16 elems per K-chunk (=128B row)
#define NCH_PASS (DIM / KCH)            // 32 chunks per pass
#define NPASS  3                        // hi*hi, lo*hi, hi*lo
#define NCHUNK (NCH_PASS * NPASS)       // 96
#define STAGES 3
#define A_BYTES (TILE_M * 128)          // 16 KB
#define B_BYTES (TILE_N * 128)          // 16 KB
#define STAGE_BYTES (A_BYTES + B_BYTES) // 32 KB
#define GTHREADS 256
#define GEMM_DYN_SMEM (STAGES * STAGE_BYTES)  // 96 KB -> 2 CTAs/SM

// -------- scratch (static device globals; runtime alloc is forbidden) ------
__device__ __nv_bfloat16 g_xh[(size_t)NTOK * DIM];   // x hi   (reused as act2 hi)
__device__ __nv_bfloat16 g_xl[(size_t)NTOK * DIM];   // x lo   (reused as act2 lo)
__device__ __nv_bfloat16 g_t1h[(size_t)NTOK * DIM];  // act1 hi
__device__ __nv_bfloat16 g_t1l[(size_t)NTOK * DIM];  // act1 lo
__device__ __nv_bfloat16 g_w1h[(size_t)DIM * DIM];
__device__ __nv_bfloat16 g_w1l[(size_t)DIM * DIM];
__device__ __nv_bfloat16 g_w3h[(size_t)DIM * DIM];
__device__ __nv_bfloat16 g_w3l[(size_t)DIM * DIM];
__device__ __nv_bfloat16 g_w2h[(size_t)DIM * DIM];
__device__ __nv_bfloat16 g_w2l[(size_t)DIM * DIM];
__device__ float g_h[(size_t)NTOK * DIM];            // final FFN output fp32
__device__ float g_C[(size_t)NTOK * NEXP];           // routing coefficients
__device__ float g_part[(size_t)(NTOK / 128) * NEXP * DIM];

// ===========================================================================
// helpers
// ===========================================================================
__device__ __forceinline__ uint32_t smem_u32(const void* p) {
    uint32_t a;
    asm("{ .reg .u64 t; cvta.to.shared.u64 t, %1; cvt.u32.u64 %0, t; }"
        : "=r"(a) : "l"(p));
    return a;
}
#define SWZ128(off) ((off) ^ (((off) >> 3) & 0x70))

__device__ __forceinline__ void cp_async16(uint32_t dst, const void* src) {
    asm volatile("cp.async.cg.shared.global [%0], [%1], 16;"
                 :: "r"(dst), "l"(src) : "memory");
}
__device__ __forceinline__ void cp_commit() {
    asm volatile("cp.async.commit_group;" ::: "memory");
}
template <int N>
__device__ __forceinline__ void cp_wait() {
    asm volatile("cp.async.wait_group %0;" :: "n"(N) : "memory");
}
__device__ __forceinline__ void ldmatrix_x4(uint32_t& r0, uint32_t& r1,
                                            uint32_t& r2, uint32_t& r3,
                                            uint32_t addr) {
    asm volatile("ldmatrix.sync.aligned.m8n8.x4.shared.b16 {%0,%1,%2,%3}, [%4];"
                 : "=r"(r0), "=r"(r1), "=r"(r2), "=r"(r3) : "r"(addr));
}
__device__ __forceinline__ void mma16816(float& d0, float& d1, float& d2, float& d3,
                                         uint32_t a0, uint32_t a1, uint32_t a2, uint32_t a3,
                                         uint32_t b0, uint32_t b1) {
    asm volatile(
        "mma.sync.aligned.m16n8k16.row.col.f32.bf16.bf16.f32 "
        "{%0,%1,%2,%3}, {%4,%5,%6,%7}, {%8,%9}, {%0,%1,%2,%3};"
        : "+f"(d0), "+f"(d1), "+f"(d2), "+f"(d3)
        : "r"(a0), "r"(a1), "r"(a2), "r"(a3), "r"(b0), "r"(b1));
}

// ===========================================================================
// split-precision GEMM:  C[M,N] = A[M,K] * B[N,K]^T  (fp32 via bf16 3-term)
//   mode 0: epilogue silu -> split into (OutH, OutL) bf16
//   mode 1: epilogue raw fp32 -> OutF
// ===========================================================================
__global__ void __launch_bounds__(GTHREADS, 2)
gemm_bf16x3(const __nv_bfloat16* __restrict__ Ah,
            const __nv_bfloat16* __restrict__ Al,
            const __nv_bfloat16* __restrict__ Bh,
            const __nv_bfloat16* __restrict__ Bl,
            __nv_bfloat16* __restrict__ OutH,
            __nv_bfloat16* __restrict__ OutL,
            float* __restrict__ OutF,
            int mode) {
    extern __shared__ char dynsm[];
    const uint32_t sm_base = smem_u32(dynsm);

    const int tid    = threadIdx.x;
    const int wid    = tid >> 5;
    const int lane   = tid & 31;
    const int warp_m = wid & 3;    // 4 row-warps: 32 rows each
    const int warp_n = wid >> 2;   // 2 col-warps: 64 cols each
    const int bm = blockIdx.y * TILE_M;
    const int bn = blockIdx.x * TILE_N;

    // fp32 accumulators: 2 m-tiles (16) x 8 n-tiles (8) x 4 regs
    float acc[2][8][4];
#pragma unroll
    for (int i = 0; i < 2; i++)
#pragma unroll
        for (int j = 0; j < 8; j++)
#pragma unroll
            for (int r = 0; r < 4; r++) acc[i][j][r] = 0.f;

    // ldmatrix per-lane byte offsets within a tile (before k16 advance+swizzle)
    uint32_t a_off[2], b_off[4];
#pragma unroll
    for (int mi = 0; mi < 2; mi++) {
        const int row = warp_m * 32 + mi * 16 + (lane & 15);
        a_off[mi] = row * 128 + (lane >> 4) * 16;
    }
#pragma unroll
    for (int g = 0; g < 4; g++) {
        const int row = warp_n * 64 + g * 16 + (lane & 15);
        b_off[g] = row * 128 + (lane >> 4) * 16;
    }

    // cp.async mapping: 2048 16B chunks per stage, 8 per thread
    auto issue_chunk = [&](int c) {
        const int pass = c >> 5;            // 0: Ah*Bh  1: Al*Bh  2: Ah*Bl
        const int k0   = (c & 31) * KCH;
        const uint32_t stage = sm_base + (uint32_t)(c % STAGES) * STAGE_BYTES;
        const __nv_bfloat16* Asrc = (pass == 1) ? Al : Ah;
        const __nv_bfloat16* Bsrc = (pass == 2) ? Bl : Bh;
#pragma unroll
        for (int i = 0; i < 4; i++) {
            const int f = tid + i * 256;
            const int r = f >> 3, v = f & 7;
            cp_async16(stage + SWZ128(r * 128 + v * 16),
                       Asrc + (size_t)(bm + r) * DIM + k0 + v * 8);
        }
#pragma unroll
        for (int i = 0; i < 4; i++) {
            const int f = tid + i * 256;
            const int r = f >> 3, v = f & 7;
            cp_async16(stage + A_BYTES + SWZ128(r * 128 + v * 16),
                       Bsrc + (size_t)(bn + r) * DIM + k0 + v * 8);
        }
    };

    // prologue: chunks 0..STAGES-2, one commit group each
#pragma unroll
    for (int c = 0; c < STAGES - 1; c++) { issue_chunk(c); cp_commit(); }

    uint32_t af[2][4];        // A frags, single-buffered (small WAR bubble)
    uint32_t bf[2][4][4];     // B frags, double-buffered across k16

    for (int c = 0; c < NCHUNK; c++) {
        cp_wait<STAGES - 2>();   // chunk c's group complete (this thread)
        __syncthreads();         // publish all copies; compute(c-1) fully done

        const uint32_t sA = sm_base + (uint32_t)(c % STAGES) * STAGE_BYTES;
        const uint32_t sB = sA + A_BYTES;

        // start k16=0 fragment loads ASAP (data is ready now)
#pragma unroll
        for (int mi = 0; mi < 2; mi++)
            ldmatrix_x4(af[mi][0], af[mi][1], af[mi][2], af[mi][3],
                        sA + SWZ128(a_off[mi]));
#pragma unroll
        for (int g = 0; g < 4; g++)
            ldmatrix_x4(bf[0][g][0], bf[0][g][1], bf[0][g][2], bf[0][g][3],
                        sB + SWZ128(b_off[g]));

        // overlap next chunk's global loads with this chunk's compute
        const int nc = c + STAGES - 1;
        if (nc < NCHUNK) issue_chunk(nc);
        cp_commit();             // one group per iteration (possibly empty)

#pragma unroll
        for (int k16 = 0; k16 < 4; k16++) {
            const int cur = k16 & 1;
            if (k16 < 3) {       // prefetch next k16's B frags into other buffer
                const uint32_t kb = (k16 + 1) * 32;
#pragma unroll
                for (int g = 0; g < 4; g++)
                    ldmatrix_x4(bf[cur ^ 1][g][0], bf[cur ^ 1][g][1],
                                bf[cur ^ 1][g][2], bf[cur ^ 1][g][3],
                                sB + SWZ128(b_off[g] + kb));
            }
#pragma unroll
            for (int mi = 0; mi < 2; mi++)
#pragma unroll
                for (int g = 0; g < 4; g++) {
                    mma16816(acc[mi][2*g][0], acc[mi][2*g][1],
                             acc[mi][2*g][2], acc[mi][2*g][3],
                             af[mi][0], af[mi][1], af[mi][2], af[mi][3],
                             bf[cur][g][0], bf[cur][g][2]);
                    mma16816(acc[mi][2*g+1][0], acc[mi][2*g+1][1],
                             acc[mi][2*g+1][2], acc[mi][2*g+1][3],
                             af[mi][0], af[mi][1], af[mi][2], af[mi][3],
                             bf[cur][g][1], bf[cur][g][3]);
                }
            if (k16 < 3) {       // reload A frags for next k16 (after last use)
                const uint32_t kb = (k16 + 1) * 32;
#pragma unroll
                for (int mi = 0; mi < 2; mi++)
                    ldmatrix_x4(af[mi][0], af[mi][1], af[mi][2], af[mi][3],
                                sA + SWZ128(a_off[mi] + kb));
            }
        }
    }

    // ---- epilogue ----
    // fragment c0,c1 -> (row, col..col+1); c2,c3 -> (row+8, col..col+1)
#pragma unroll
    for (int mi = 0; mi < 2; mi++) {
        const int row0 = bm + warp_m * 32 + mi * 16 + (lane >> 2);
#pragma unroll
        for (int ni = 0; ni < 8; ni++) {
            const int col = bn + warp_n * 64 + ni * 8 + (lane & 3) * 2;
#pragma unroll
            for (int half = 0; half < 2; half++) {
                const int row = row0 + half * 8;
                const size_t idx = (size_t)row * DIM + col;
                float v0 = acc[mi][ni][half * 2 + 0];
                float v1 = acc[mi][ni][half * 2 + 1];
                if (mode == 0) {
                    v0 = v0 / (1.f + expf(-v0));
                    v1 = v1 / (1.f + expf(-v1));
                    __nv_bfloat16 h0 = __float2bfloat16(v0);
                    __nv_bfloat16 h1 = __float2bfloat16(v1);
                    __nv_bfloat16 l0 = __float2bfloat16(v0 - __bfloat162float(h0));
                    __nv_bfloat16 l1 = __float2bfloat16(v1 - __bfloat162float(h1));
                    *(__nv_bfloat162*)(OutH + idx) = __halves2bfloat162(h0, h1);
                    *(__nv_bfloat162*)(OutL + idx) = __halves2bfloat162(l0, l1);
                } else {
                    *(float2*)(OutF + idx) = make_float2(v0, v1);
                }
            }
        }
    }
}

// ===========================================================================
// fp32 -> (hi, lo) bf16 split, vectorized
// ===========================================================================
__global__ void split_kernel(const float4* __restrict__ in,
                             __nv_bfloat162* __restrict__ hi,
                             __nv_bfloat162* __restrict__ lo, int n4) {
    int i = blockIdx.x * blockDim.x + threadIdx.x;
    const int stride = gridDim.x * blockDim.x;
    for (; i < n4; i += stride) {
        float4 v = in[i];
        __nv_bfloat16 h0 = __float2bfloat16(v.x), h1 = __float2bfloat16(v.y);
        __nv_bfloat16 h2 = __float2bfloat16(v.z), h3 = __float2bfloat16(v.w);
        __nv_bfloat16 l0 = __float2bfloat16(v.x - __bfloat162float(h0));
        __nv_bfloat16 l1 = __float2bfloat16(v.y - __bfloat162float(h1));
        __nv_bfloat16 l2 = __float2bfloat16(v.z - __bfloat162float(h2));
        __nv_bfloat16 l3 = __float2bfloat16(v.w - __bfloat162float(h3));
        hi[2 * i]     = __halves2bfloat162(h0, h1);
        hi[2 * i + 1] = __halves2bfloat162(h2, h3);
        lo[2 * i]     = __halves2bfloat162(l0, l1);
        lo[2 * i + 1] = __halves2bfloat162(l2, l3);
    }
}

// ===========================================================================
// zero-fill output
// ===========================================================================
__global__ void zero_kernel(float4* __restrict__ out, size_t n4) {
    size_t i = (size_t)blockIdx.x * blockDim.x + threadIdx.x;
    size_t stride = (size_t)gridDim.x * blockDim.x;
    float4 z = make_float4(0.f, 0.f, 0.f, 0.f);
    for (; i < n4; i += stride) out[i] = z;
}

// ===========================================================================
// routing: one warp per token; softmax -> top2 -> normalized gates
// ===========================================================================
__global__ void routing_kernel(const float* __restrict__ x,
                               const float* __restrict__ wr,
                               float* __restrict__ C) {
    int gwarp = (blockIdx.x * blockDim.x + threadIdx.x) >> 5;
    int lane  = threadIdx.x & 31;
    if (gwarp >= NTOK) return;
    const float* xr = x + (size_t)gwarp * DIM;
    float acc[NEXP];
#pragma unroll
    for (int e = 0; e < NEXP; e++) acc[e] = 0.f;
    for (int k = lane; k < DIM; k += 32) {
        float xv = xr[k];
#pragma unroll
        for (int e = 0; e < NEXP; e++)
            acc[e] = fmaf(xv, wr[e * DIM + k], acc[e]);
    }
#pragma unroll
    for (int e = 0; e < NEXP; e++) {
#pragma unroll
        for (int off = 16; off > 0; off >>= 1)
            acc[e] += __shfl_xor_sync(0xffffffffu, acc[e], off);
    }
    if (lane == 0) {
        float m = acc[0];
#pragma unroll
        for (int e = 1; e < NEXP; e++) m = fmaxf(m, acc[e]);
        float p[NEXP];
#pragma unroll
        for (int e = 0; e < NEXP; e++) p[e] = expf(acc[e] - m);
        int e0 = 0; float p0 = p[0];
#pragma unroll
        for (int e = 1; e < NEXP; e++) if (p[e] > p0) { p0 = p[e]; e0 = e; }
        int e1 = -1; float p1 = -1.f;
#pragma unroll
        for (int e = 0; e < NEXP; e++)
            if (e != e0 && p[e] > p1) { p1 = p[e]; e1 = e; }
        float inv = 1.f / (p0 + p1);
        float* Cn = C + (size_t)gwarp * NEXP;
#pragma unroll
        for (int e = 0; e < NEXP; e++) {
            float v = 0.f;
            if (e == e0) v = p0 * inv;
            else if (e == e1) v = p1 * inv;
            Cn[e] = v;
        }
    }
}

// ===========================================================================
// expert-weighted reduction (two-stage, deterministic)
// ===========================================================================
__global__ void reduce_partial_kernel(const float* __restrict__ h,
                                      const float* __restrict__ C,
                                      float* __restrict__ part) {
    const int col = blockIdx.x * 128 + threadIdx.x;
    const int n0 = blockIdx.y * 128;
    float acc[NEXP];
#pragma unroll
    for (int e = 0; e < NEXP; e++) acc[e] = 0.f;
    for (int i = 0; i < 128; i++) {
        const int n = n0 + i;
        const float hv = h[(size_t)n * DIM + col];
        const float* Cn = C + (size_t)n * NEXP;
#pragma unroll
        for (int e = 0; e < NEXP; e++)
            acc[e] = fmaf(hv, Cn[e], acc[e]);
    }
#pragma unroll
    for (int e = 0; e < NEXP; e++)
        part[((size_t)blockIdx.y * NEXP + e) * DIM + col] = acc[e];
}

__global__ void reduce_final_kernel(const float* __restrict__ part,
                                    float* __restrict__ out) {
    const int id = blockIdx.x * blockDim.x + threadIdx.x;
    if (id >= NEXP * DIM) return;
    const int e = id / DIM;
    const int col = id % DIM;
    float s = 0.f;
#pragma unroll 4
    for (int by = 0; by < NTOK / 128; by++)
        s += part[((size_t)by * NEXP + e) * DIM + col];
    out[(size_t)e * DIM + col] = s;
}

// ===========================================================================
extern "C" void kernel_launch(void* const* d_in, const int* in_sizes, int n_in,
                              void* d_out, int out_size) {
    const float* x  = (const float*)d_in[0];
    const float* w1 = (const float*)d_in[1];
    const float* w3 = (const float*)d_in[2];
    const float* w2 = (const float*)d_in[3];
    const float* wr = (const float*)d_in[4];
    float* out = (float*)d_out;

    __nv_bfloat16 *xh, *xl, *t1h, *t1l, *w1h, *w1l, *w3h, *w3l, *w2h, *w2l;
    float *hbuf, *C, *part;
    cudaGetSymbolAddress((void**)&xh,  g_xh);
    cudaGetSymbolAddress((void**)&xl,  g_xl);
    cudaGetSymbolAddress((void**)&t1h, g_t1h);
    cudaGetSymbolAddress((void**)&t1l, g_t1l);
    cudaGetSymbolAddress((void**)&w1h, g_w1h);
    cudaGetSymbolAddress((void**)&w1l, g_w1l);
    cudaGetSymbolAddress((void**)&w3h, g_w3h);
    cudaGetSymbolAddress((void**)&w3l, g_w3l);
    cudaGetSymbolAddress((void**)&w2h, g_w2h);
    cudaGetSymbolAddress((void**)&w2l, g_w2l);
    cudaGetSymbolAddress((void**)&hbuf, g_h);
    cudaGetSymbolAddress((void**)&C,    g_C);
    cudaGetSymbolAddress((void**)&part, g_part);

    cudaFuncSetAttribute(gemm_bf16x3,
                         cudaFuncAttributeMaxDynamicSharedMemorySize,
                         GEMM_DYN_SMEM);

    // 1) zero output (harness poisons it)
    {
        size_t n4 = (size_t)out_size / 4;
        int blocks = (int)((n4 + 255) / 256);
        if (blocks > 16384) blocks = 16384;
        zero_kernel<<<blocks, 256>>>((float4*)out, n4);
    }

    // 2) routing coefficients (fp32, faithful top-k)
    routing_kernel<<<(NTOK * 32) / 256, 256>>>(x, wr, C);

    // 3) hi/lo splits
    const int nx4 = NTOK * DIM / 4, nw4 = DIM * DIM / 4;
    split_kernel<<<2048, 256>>>((const float4*)x,  (__nv_bfloat162*)xh,  (__nv_bfloat162*)xl,  nx4);
    split_kernel<<<1024, 256>>>((const float4*)w1, (__nv_bfloat162*)w1h, (__nv_bfloat162*)w1l, nw4);
    split_kernel<<<1024, 256>>>((const float4*)w3, (__nv_bfloat162*)w3h, (__nv_bfloat162*)w3l, nw4);
    split_kernel<<<1024, 256>>>((const float4*)w2, (__nv_bfloat162*)w2h, (__nv_bfloat162*)w2l, nw4);

    // 4) FFN chain on tensor cores (mma.sync path)
    dim3 ggrid(DIM / TILE_N, NTOK / TILE_M);  // (16, 64)
    gemm_bf16x3<<<ggrid, GTHREADS, GEMM_DYN_SMEM>>>(xh, xl, w1h, w1l,
                                                    t1h, t1l, nullptr, 0);
    gemm_bf16x3<<<ggrid, GTHREADS, GEMM_DYN_SMEM>>>(t1h, t1l, w3h, w3l,
                                                    xh, xl, nullptr, 0);   // reuse x bufs
    gemm_bf16x3<<<ggrid, GTHREADS, GEMM_DYN_SMEM>>>(xh, xl, w2h, w2l,
                                                    nullptr, nullptr, hbuf, 1);

    // 5) expert-weighted reduction into rows 0..7
    reduce_partial_kernel<<<dim3(DIM / 128, NTOK / 128), 128>>>(hbuf, C, part);
    reduce_final_kernel<<<(NEXP * DIM + 255) / 256, 256>>>(part, out);
}